// round 8
// baseline (speedup 1.0000x reference)
#include <cuda_runtime.h>
#include <cstdint>

#define B_  4
#define N_  2048
#define D_  128
#define GRID 148
#define UNITS 1024   // 4 b * 16 slabs * 16 j-tiles

// smem layout (bytes)
#define SM_SQ  0
#define SM_A   8192
#define SM_B0  (8192 + 65536)
#define SM_B1  (8192 + 2 * 65536)
#define SM_TOTAL (8192 + 3 * 65536)

__device__ float g_sq[B_ * N_];

// warp-per-row squared norms
__global__ void sq_kernel(const float* __restrict__ x) {
    int wid = threadIdx.x >> 5, lane = threadIdx.x & 31;
    int row = blockIdx.x * 8 + wid;
    float4 v = *(const float4*)(x + (size_t)row * D_ + lane * 4);
    float s = v.x * v.x + v.y * v.y + v.z * v.z + v.w * v.w;
#pragma unroll
    for (int o = 16; o > 0; o >>= 1) s += __shfl_xor_sync(0xffffffffu, s, o);
    if (lane == 0) g_sq[row] = s;
}

__device__ __forceinline__ float fsqrt_approx(float a) {
    float r;
    asm("sqrt.approx.f32 %0, %1;" : "=f"(r) : "f"(a));
    return r;
}

// convert one 128-row x 128-col fp32 tile into pair-interleaved swizzled smem
// slot s = 4*kbi + c holds (x[8*kbi+c], x[8*kbi+c+4]); phys = s ^ ((r&3)<<2)
// 512 threads: each thread owns one (r, aa) pair, iterates 4 kbi groups.
__device__ __forceinline__ void load_tile(const float* __restrict__ gbase,
                                          char* __restrict__ sbase, int tid) {
    const int bb = tid & 3;
    const int aa = (tid >> 2) & 3;
    const int r = bb | ((tid >> 4) << 2);    // 0..127
    const int x4 = (r & 3) << 2;
    char* rowS = sbase + r * 512;
    const float* rowG = gbase + (size_t)r * D_;
#pragma unroll
    for (int iter = 0; iter < 4; iter++) {
        int kbi = aa | (iter << 2);          // 0..15
        float4 v0 = *(const float4*)(rowG + kbi * 8);
        float4 v1 = *(const float4*)(rowG + kbi * 8 + 4);
        float va[8] = {v0.x, v0.y, v0.z, v0.w, v1.x, v1.y, v1.z, v1.w};
#pragma unroll
        for (int j = 0; j < 4; j++) {
            int c = (bb + j) & 3;
            int phys = (4 * kbi + c) ^ x4;
            *(float2*)(rowS + phys * 8) = make_float2(va[c], va[c + 4]);
        }
    }
}

__global__ __launch_bounds__(512) void edm_mma_kernel(const float* __restrict__ x,
                                                      float* __restrict__ out) {
    extern __shared__ char smem[];
    const int tid = threadIdx.x;
    const int wid = tid >> 5;
    const int lane = tid & 31;
    const int g  = lane >> 2;   // 0..7
    const int cc = lane & 3;    // 0..3

    const int wm = (wid & 3) * 32;    // 0,32,64,96
    const int wn = (wid >> 2) * 32;   // 0,32,64,96
    const int gx4 = (g & 3) << 2;
    const float* sq_s = (const float*)(smem + SM_SQ);

    // loader mapping (matches load_tile)
    const int bb = tid & 3;
    const int aa = (tid >> 2) & 3;
    const int pr = bb | ((tid >> 4) << 2);   // 0..127
    const int px4 = (pr & 3) << 2;

    const int us = (UNITS * blockIdx.x) / GRID;
    const int ue = (UNITS * (blockIdx.x + 1)) / GRID;

    int key = -1;
    int p = 0;

#pragma unroll 1
    for (int u = us; u < ue; u++) {
        const int b    = u >> 8;
        const int slab = (u >> 4) & 15;
        const int jt   = u & 15;
        const int k2   = u >> 4;
        const float* xb = x + (size_t)b * N_ * D_;

        if (k2 != key) {
            __syncthreads();
            ((float4*)(smem + SM_SQ))[tid] = ((const float4*)(g_sq + b * N_))[tid];
            load_tile(xb + (size_t)slab * 128 * D_, smem + SM_A, tid);
            load_tile(xb + (size_t)jt * 128 * D_, smem + (p ? SM_B1 : SM_B0), tid);
            __syncthreads();
            key = k2;
        }
        char* bufC = smem + (p ? SM_B1 : SM_B0);
        char* bufN = smem + (p ? SM_B0 : SM_B1);

        // ---- mainloop: warp tile 32x32, m16n8k8 tf32, software-pipelined ----
        float acc[2][4][4];
#pragma unroll
        for (int mt = 0; mt < 2; mt++)
#pragma unroll
            for (int nt = 0; nt < 4; nt++)
#pragma unroll
                for (int e = 0; e < 4; e++) acc[mt][nt][e] = 0.f;

        uint32_t a[2][2][4], bf[2][4][2];

        // prologue: load k-step 0 fragments
        {
            const int phys = cc ^ gx4;
#pragma unroll
            for (int mt = 0; mt < 2; mt++) {
                int r0 = wm + 16 * mt + g;
                float2 a02 = *(float2*)(smem + SM_A + r0 * 512 + phys * 8);
                float2 a13 = *(float2*)(smem + SM_A + (r0 + 8) * 512 + phys * 8);
                a[0][mt][0] = __float_as_uint(a02.x);
                a[0][mt][1] = __float_as_uint(a13.x);
                a[0][mt][2] = __float_as_uint(a02.y);
                a[0][mt][3] = __float_as_uint(a13.y);
            }
#pragma unroll
            for (int nt = 0; nt < 4; nt++) {
                int n0 = wn + 8 * nt + g;
                float2 b01 = *(float2*)(bufC + n0 * 512 + phys * 8);
                bf[0][nt][0] = __float_as_uint(b01.x);
                bf[0][nt][1] = __float_as_uint(b01.y);
            }
        }

#pragma unroll
        for (int kst = 0; kst < 16; kst++) {
            const int cur = kst & 1, nxt = cur ^ 1;
            if (kst < 15) {
                const int phys = (4 * (kst + 1) + cc) ^ gx4;
#pragma unroll
                for (int mt = 0; mt < 2; mt++) {
                    int r0 = wm + 16 * mt + g;
                    float2 a02 = *(float2*)(smem + SM_A + r0 * 512 + phys * 8);
                    float2 a13 = *(float2*)(smem + SM_A + (r0 + 8) * 512 + phys * 8);
                    a[nxt][mt][0] = __float_as_uint(a02.x);
                    a[nxt][mt][1] = __float_as_uint(a13.x);
                    a[nxt][mt][2] = __float_as_uint(a02.y);
                    a[nxt][mt][3] = __float_as_uint(a13.y);
                }
#pragma unroll
                for (int nt = 0; nt < 4; nt++) {
                    int n0 = wn + 8 * nt + g;
                    float2 b01 = *(float2*)(bufC + n0 * 512 + phys * 8);
                    bf[nxt][nt][0] = __float_as_uint(b01.x);
                    bf[nxt][nt][1] = __float_as_uint(b01.y);
                }
            }
#pragma unroll
            for (int mt = 0; mt < 2; mt++)
#pragma unroll
                for (int nt = 0; nt < 4; nt++) {
                    asm volatile(
                        "mma.sync.aligned.m16n8k8.row.col.f32.tf32.tf32.f32 "
                        "{%0,%1,%2,%3}, {%4,%5,%6,%7}, {%8,%9}, {%0,%1,%2,%3};"
                        : "+f"(acc[mt][nt][0]), "+f"(acc[mt][nt][1]),
                          "+f"(acc[mt][nt][2]), "+f"(acc[mt][nt][3])
                        : "r"(a[cur][mt][0]), "r"(a[cur][mt][1]),
                          "r"(a[cur][mt][2]), "r"(a[cur][mt][3]),
                          "r"(bf[cur][nt][0]), "r"(bf[cur][nt][1]));
                }
        }

        // ---- prefetch next unit's B tile into regs (same slab only) ----
        const bool pf_ok = (u + 1 < ue) && ((u + 1) >> 4 == k2);
        float4 pf[4][2];
        if (pf_ok) {
            const int njt = (u + 1) & 15;
            const float* rowG = xb + (size_t)(njt * 128 + pr) * D_;
#pragma unroll
            for (int iter = 0; iter < 4; iter++) {
                int kbi = aa | (iter << 2);
                pf[iter][0] = *(const float4*)(rowG + kbi * 8);
                pf[iter][1] = *(const float4*)(rowG + kbi * 8 + 4);
            }
        }

        // ---- epilogue: d = sqrt(max(sqi + sqj - 2*dot, 0) + eps) ----
        {
            float2 sqj2[4];
            const int sjb = jt * 128 + wn;
#pragma unroll
            for (int nt = 0; nt < 4; nt++)
                sqj2[nt] = *(const float2*)&sq_s[sjb + 8 * nt + 2 * cc];
#pragma unroll
            for (int mt = 0; mt < 2; mt++) {
#pragma unroll
                for (int h = 0; h < 2; h++) {
                    int row = wm + 16 * mt + 8 * h + g;
                    float si = sq_s[slab * 128 + row];
                    float* orow = out + ((size_t)(b * N_ + slab * 128 + row)) * N_ +
                                  jt * 128 + wn;
#pragma unroll
                    for (int nt = 0; nt < 4; nt++) {
                        float d0 = acc[mt][nt][2 * h];
                        float d1 = acc[mt][nt][2 * h + 1];
                        float v0 = fsqrt_approx(fmaxf(fmaf(-2.f, d0, si + sqj2[nt].x), 0.f) + 1e-7f);
                        float v1 = fsqrt_approx(fmaxf(fmaf(-2.f, d1, si + sqj2[nt].y), 0.f) + 1e-7f);
                        *(float2*)(orow + 8 * nt + 2 * cc) = make_float2(v0, v1);
                    }
                }
            }
        }

        // ---- store prefetched tile into the other buffer ----
        if (pf_ok) {
            char* rowS = bufN + pr * 512;
#pragma unroll
            for (int iter = 0; iter < 4; iter++) {
                int kbi = aa | (iter << 2);
                float va[8] = {pf[iter][0].x, pf[iter][0].y, pf[iter][0].z, pf[iter][0].w,
                               pf[iter][1].x, pf[iter][1].y, pf[iter][1].z, pf[iter][1].w};
#pragma unroll
                for (int j2 = 0; j2 < 4; j2++) {
                    int c = (bb + j2) & 3;
                    int phys = (4 * kbi + c) ^ px4;
                    *(float2*)(rowS + phys * 8) = make_float2(va[c], va[c + 4]);
                }
            }
            __syncthreads();
            p ^= 1;
        }
    }
}

extern "C" void kernel_launch(void* const* d_in, const int* in_sizes, int n_in,
                              void* d_out, int out_size) {
    const float* x = (const float*)d_in[0];
    float* out = (float*)d_out;

    sq_kernel<<<B_ * N_ / 8, 256>>>(x);

    cudaFuncSetAttribute(edm_mma_kernel, cudaFuncAttributeMaxDynamicSharedMemorySize, SM_TOTAL);
    edm_mma_kernel<<<GRID, 512, SM_TOTAL>>>(x, out);
}

// round 9
// speedup vs baseline: 1.4121x; 1.4121x over previous
#include <cuda_runtime.h>
#include <cstdint>

#define B_  4
#define N_  2048
#define D_  128

// smem layout (bytes)
#define SM_SQI 0
#define SM_SQJ 512
#define SM_A   8192
#define SM_B0  (8192 + 65536)
#define SM_B1  (8192 + 2 * 65536)
#define SM_TOTAL (8192 + 3 * 65536)

__device__ float g_sq[B_ * N_];
// pre-swizzled tiles: [b*16 + tile][row 0..127][512 bytes]
__device__ __align__(16) char g_xs[B_ * 16 * 128 * 512];

// preprocess: per row, compute squared norm AND write pair-interleaved swizzled layout
// slot s = 4*kbi + c holds (x[8*kbi+c], x[8*kbi+c+4]); phys = s ^ ((r&3)<<2)
__global__ void prep_kernel(const float* __restrict__ x) {
    int wid = threadIdx.x >> 5, lane = threadIdx.x & 31;
    int row = blockIdx.x * 8 + wid;          // 0 .. B_*N_-1
    float4 v = *(const float4*)(x + (size_t)row * D_ + lane * 4);

    float s = v.x * v.x + v.y * v.y + v.z * v.z + v.w * v.w;
#pragma unroll
    for (int o = 16; o > 0; o >>= 1) s += __shfl_xor_sync(0xffffffffu, s, o);
    if (lane == 0) g_sq[row] = s;

    float4 u;
    u.x = __shfl_xor_sync(0xffffffffu, v.x, 1);
    u.y = __shfl_xor_sync(0xffffffffu, v.y, 1);
    u.z = __shfl_xor_sync(0xffffffffu, v.z, 1);
    u.w = __shfl_xor_sync(0xffffffffu, v.w, 1);

    const int r = row & 127;
    const int x4 = (r & 3) << 2;
    char* rowS = g_xs + (size_t)(row >> 7) * 65536 + r * 512;
    const int kbi = lane >> 1;
    if ((lane & 1) == 0) {
        *(float2*)(rowS + ((4 * kbi + 0) ^ x4) * 8) = make_float2(v.x, u.x);
        *(float2*)(rowS + ((4 * kbi + 1) ^ x4) * 8) = make_float2(v.y, u.y);
    } else {
        *(float2*)(rowS + ((4 * kbi + 2) ^ x4) * 8) = make_float2(u.z, v.z);
        *(float2*)(rowS + ((4 * kbi + 3) ^ x4) * 8) = make_float2(u.w, v.w);
    }
}

__device__ __forceinline__ float fsqrt_approx(float a) {
    float r;
    asm("sqrt.approx.f32 %0, %1;" : "=f"(r) : "f"(a));
    return r;
}

__device__ __forceinline__ void cp16(uint32_t s, const char* g) {
    asm volatile("cp.async.cg.shared.global [%0], [%1], 16;" :: "r"(s), "l"(g));
}

// copy one 64KB pre-swizzled tile global->smem via cp.async (512 threads)
__device__ __forceinline__ void tile_cp(uint32_t sdst, const char* gsrc, int tid) {
#pragma unroll
    for (int i = 0; i < 8; i++)
        cp16(sdst + tid * 16 + i * 8192, gsrc + tid * 16 + i * 8192);
}

__global__ __launch_bounds__(512) void edm_mma_kernel(float* __restrict__ out) {
    extern __shared__ char smem[];
    const uint32_t smem_b = (uint32_t)__cvta_generic_to_shared(smem);
    const int tid = threadIdx.x;
    const int wid = tid >> 5;
    const int lane = tid & 31;
    const int g  = lane >> 2;   // 0..7
    const int cc = lane & 3;    // 0..3

    const int half = blockIdx.x;             // 0..1
    const int slab = blockIdx.y;             // 0..15
    const int b    = blockIdx.z;
    const int i0   = slab * 128;
    const int jbase = half * 1024;
    const char* xs_b = g_xs + (size_t)b * 16 * 65536;

    // ---- prologue: A slab + B tile 0 via cp.async, norms via LDG ----
    tile_cp(smem_b + SM_A, xs_b + (size_t)slab * 65536, tid);
    tile_cp(smem_b + SM_B0, xs_b + (size_t)(half * 8) * 65536, tid);
    asm volatile("cp.async.commit_group;");
    if (tid < 128) ((float*)(smem + SM_SQI))[tid] = g_sq[b * N_ + i0 + tid];
    ((float*)(smem + SM_SQJ))[tid]       = g_sq[b * N_ + jbase + tid];
    ((float*)(smem + SM_SQJ))[tid + 512] = g_sq[b * N_ + jbase + tid + 512];
    asm volatile("cp.async.wait_group 0;");
    __syncthreads();

    const int wm = (wid & 3) * 32;    // 0,32,64,96
    const int wn = (wid >> 2) * 32;   // 0,32,64,96
    const int gx4 = (g & 3) << 2;
    const float* sqi_s = (const float*)(smem + SM_SQI);
    const float* sqj_s = (const float*)(smem + SM_SQJ);

#pragma unroll 1
    for (int jj = 0; jj < 8; jj++) {
        char* bufC = smem + (jj & 1 ? SM_B1 : SM_B0);
        const uint32_t bufN = smem_b + (jj & 1 ? SM_B0 : SM_B1);

        // issue next B tile copy; it flows during the mainloop
        if (jj < 7) {
            tile_cp(bufN, xs_b + (size_t)(half * 8 + jj + 1) * 65536, tid);
            asm volatile("cp.async.commit_group;");
        }

        // ---- mainloop: warp tile 32x32, m16n8k8 tf32, pipelined frags ----
        float acc[2][4][4];
#pragma unroll
        for (int mt = 0; mt < 2; mt++)
#pragma unroll
            for (int nt = 0; nt < 4; nt++)
#pragma unroll
                for (int e = 0; e < 4; e++) acc[mt][nt][e] = 0.f;

        uint32_t a[2][2][4], bf[2][4][2];
        {
            const int phys = cc ^ gx4;
#pragma unroll
            for (int mt = 0; mt < 2; mt++) {
                int r0 = wm + 16 * mt + g;
                float2 a02 = *(float2*)(smem + SM_A + r0 * 512 + phys * 8);
                float2 a13 = *(float2*)(smem + SM_A + (r0 + 8) * 512 + phys * 8);
                a[0][mt][0] = __float_as_uint(a02.x);
                a[0][mt][1] = __float_as_uint(a13.x);
                a[0][mt][2] = __float_as_uint(a02.y);
                a[0][mt][3] = __float_as_uint(a13.y);
            }
#pragma unroll
            for (int nt = 0; nt < 4; nt++) {
                int n0 = wn + 8 * nt + g;
                float2 b01 = *(float2*)(bufC + n0 * 512 + phys * 8);
                bf[0][nt][0] = __float_as_uint(b01.x);
                bf[0][nt][1] = __float_as_uint(b01.y);
            }
        }

#pragma unroll
        for (int kst = 0; kst < 16; kst++) {
            const int cur = kst & 1, nxt = cur ^ 1;
            if (kst < 15) {
                const int phys = (4 * (kst + 1) + cc) ^ gx4;
#pragma unroll
                for (int mt = 0; mt < 2; mt++) {
                    int r0 = wm + 16 * mt + g;
                    float2 a02 = *(float2*)(smem + SM_A + r0 * 512 + phys * 8);
                    float2 a13 = *(float2*)(smem + SM_A + (r0 + 8) * 512 + phys * 8);
                    a[nxt][mt][0] = __float_as_uint(a02.x);
                    a[nxt][mt][1] = __float_as_uint(a13.x);
                    a[nxt][mt][2] = __float_as_uint(a02.y);
                    a[nxt][mt][3] = __float_as_uint(a13.y);
                }
#pragma unroll
                for (int nt = 0; nt < 4; nt++) {
                    int n0 = wn + 8 * nt + g;
                    float2 b01 = *(float2*)(bufC + n0 * 512 + phys * 8);
                    bf[nxt][nt][0] = __float_as_uint(b01.x);
                    bf[nxt][nt][1] = __float_as_uint(b01.y);
                }
            }
#pragma unroll
            for (int mt = 0; mt < 2; mt++)
#pragma unroll
                for (int nt = 0; nt < 4; nt++) {
                    asm volatile(
                        "mma.sync.aligned.m16n8k8.row.col.f32.tf32.tf32.f32 "
                        "{%0,%1,%2,%3}, {%4,%5,%6,%7}, {%8,%9}, {%0,%1,%2,%3};"
                        : "+f"(acc[mt][nt][0]), "+f"(acc[mt][nt][1]),
                          "+f"(acc[mt][nt][2]), "+f"(acc[mt][nt][3])
                        : "r"(a[cur][mt][0]), "r"(a[cur][mt][1]),
                          "r"(a[cur][mt][2]), "r"(a[cur][mt][3]),
                          "r"(bf[cur][nt][0]), "r"(bf[cur][nt][1]));
                }
        }

        // ---- epilogue: d = sqrt(max(sqi + sqj - 2*dot, 0) + eps) ----
        {
            float2 sqj2[4];
            const int sjb = jj * 128 + wn;
#pragma unroll
            for (int nt = 0; nt < 4; nt++)
                sqj2[nt] = *(const float2*)&sqj_s[sjb + 8 * nt + 2 * cc];
#pragma unroll
            for (int mt = 0; mt < 2; mt++) {
#pragma unroll
                for (int h = 0; h < 2; h++) {
                    int row = wm + 16 * mt + 8 * h + g;
                    float si = sqi_s[row];
                    float* orow = out + ((size_t)(b * N_ + i0 + row)) * N_ +
                                  jbase + jj * 128 + wn;
#pragma unroll
                    for (int nt = 0; nt < 4; nt++) {
                        float d0 = acc[mt][nt][2 * h];
                        float d1 = acc[mt][nt][2 * h + 1];
                        float v0 = fsqrt_approx(fmaxf(fmaf(-2.f, d0, si + sqj2[nt].x), 0.f) + 1e-7f);
                        float v1 = fsqrt_approx(fmaxf(fmaf(-2.f, d1, si + sqj2[nt].y), 0.f) + 1e-7f);
                        *(float2*)(orow + 8 * nt + 2 * cc) = make_float2(v0, v1);
                    }
                }
            }
        }

        if (jj < 7) {
            asm volatile("cp.async.wait_group 0;");
            __syncthreads();
        }
    }
}

extern "C" void kernel_launch(void* const* d_in, const int* in_sizes, int n_in,
                              void* d_out, int out_size) {
    const float* x = (const float*)d_in[0];
    float* out = (float*)d_out;

    prep_kernel<<<B_ * N_ / 8, 256>>>(x);

    cudaFuncSetAttribute(edm_mma_kernel, cudaFuncAttributeMaxDynamicSharedMemorySize, SM_TOTAL);
    dim3 grid(2, 16, B_);
    edm_mma_kernel<<<grid, 512, SM_TOTAL>>>(out);
}

// round 10
// speedup vs baseline: 1.4992x; 1.0617x over previous
#include <cuda_runtime.h>
#include <cstdint>

#define B_  4
#define N_  2048
#define D_  128

// smem layout (bytes)
#define SM_SQI 0
#define SM_SQJ 512
#define SM_A   8192
#define SM_B0  (8192 + 65536)
#define SM_B1  (8192 + 2 * 65536)
#define SM_TOTAL (8192 + 3 * 65536)

__device__ float g_sq[B_ * N_];
// pre-swizzled tiles: [b*16 + tile][row 0..127][512 bytes]
__device__ __align__(16) char g_xs[B_ * 16 * 128 * 512];

// preprocess: per row, compute squared norm AND write pair-interleaved swizzled layout
// slot s = 4*kbi + c holds (x[8*kbi+c], x[8*kbi+c+4]); phys = s ^ ((r&3)<<2)
__global__ void prep_kernel(const float* __restrict__ x) {
    int wid = threadIdx.x >> 5, lane = threadIdx.x & 31;
    int row = blockIdx.x * 8 + wid;          // 0 .. B_*N_-1
    float4 v = *(const float4*)(x + (size_t)row * D_ + lane * 4);

    float s = v.x * v.x + v.y * v.y + v.z * v.z + v.w * v.w;
#pragma unroll
    for (int o = 16; o > 0; o >>= 1) s += __shfl_xor_sync(0xffffffffu, s, o);
    if (lane == 0) g_sq[row] = s;

    float4 u;
    u.x = __shfl_xor_sync(0xffffffffu, v.x, 1);
    u.y = __shfl_xor_sync(0xffffffffu, v.y, 1);
    u.z = __shfl_xor_sync(0xffffffffu, v.z, 1);
    u.w = __shfl_xor_sync(0xffffffffu, v.w, 1);

    const int r = row & 127;
    const int x4 = (r & 3) << 2;
    char* rowS = g_xs + (size_t)(row >> 7) * 65536 + r * 512;
    const int kbi = lane >> 1;
    if ((lane & 1) == 0) {
        *(float2*)(rowS + ((4 * kbi + 0) ^ x4) * 8) = make_float2(v.x, u.x);
        *(float2*)(rowS + ((4 * kbi + 1) ^ x4) * 8) = make_float2(v.y, u.y);
    } else {
        *(float2*)(rowS + ((4 * kbi + 2) ^ x4) * 8) = make_float2(u.z, v.z);
        *(float2*)(rowS + ((4 * kbi + 3) ^ x4) * 8) = make_float2(u.w, v.w);
    }
}

__device__ __forceinline__ float fsqrt_approx(float a) {
    float r;
    asm("sqrt.approx.f32 %0, %1;" : "=f"(r) : "f"(a));
    return r;
}

__device__ __forceinline__ void cp16(uint32_t s, const char* g) {
    asm volatile("cp.async.cg.shared.global [%0], [%1], 16;" :: "r"(s), "l"(g));
}

// copy one 64KB pre-swizzled tile global->smem via cp.async (256 threads)
__device__ __forceinline__ void tile_cp(uint32_t sdst, const char* gsrc, int tid) {
#pragma unroll
    for (int i = 0; i < 16; i++)
        cp16(sdst + tid * 16 + i * 4096, gsrc + tid * 16 + i * 4096);
}

__global__ __launch_bounds__(256, 1) void edm_mma_kernel(float* __restrict__ out) {
    extern __shared__ char smem[];
    const uint32_t smem_b = (uint32_t)__cvta_generic_to_shared(smem);
    const int tid = threadIdx.x;
    const int wid = tid >> 5;
    const int lane = tid & 31;
    const int g  = lane >> 2;   // 0..7
    const int cc = lane & 3;    // 0..3

    const int half = blockIdx.x;             // 0..1
    const int slab = blockIdx.y;             // 0..15
    const int b    = blockIdx.z;
    const int i0   = slab * 128;
    const int jbase = half * 1024;
    const char* xs_b = g_xs + (size_t)b * 16 * 65536;

    // ---- prologue: A slab + B tile 0 via cp.async, norms via LDG ----
    tile_cp(smem_b + SM_A, xs_b + (size_t)slab * 65536, tid);
    tile_cp(smem_b + SM_B0, xs_b + (size_t)(half * 8) * 65536, tid);
    asm volatile("cp.async.commit_group;");
    if (tid < 128) ((float*)(smem + SM_SQI))[tid] = g_sq[b * N_ + i0 + tid];
#pragma unroll
    for (int k = 0; k < 4; k++)
        ((float*)(smem + SM_SQJ))[tid + k * 256] = g_sq[b * N_ + jbase + tid + k * 256];
    asm volatile("cp.async.wait_group 0;");
    __syncthreads();

    const int wm = (wid & 1) * 64;    // 0,64
    const int wn = (wid >> 1) * 32;   // 0,32,64,96
    const int gx4 = (g & 3) << 2;
    const float* sqi_s = (const float*)(smem + SM_SQI);
    const float* sqj_s = (const float*)(smem + SM_SQJ);

#pragma unroll 1
    for (int jj = 0; jj < 8; jj++) {
        char* bufC = smem + (jj & 1 ? SM_B1 : SM_B0);
        const uint32_t bufN = smem_b + (jj & 1 ? SM_B0 : SM_B1);

        // issue next B tile copy; it flows during the mainloop
        if (jj < 7) {
            tile_cp(bufN, xs_b + (size_t)(half * 8 + jj + 1) * 65536, tid);
            asm volatile("cp.async.commit_group;");
        }

        // ---- mainloop: warp tile 64x32, m16n8k8 tf32, pipelined frags ----
        float acc[4][4][4];
#pragma unroll
        for (int mt = 0; mt < 4; mt++)
#pragma unroll
            for (int nt = 0; nt < 4; nt++)
#pragma unroll
                for (int e = 0; e < 4; e++) acc[mt][nt][e] = 0.f;

        uint32_t a[2][4][4], bf[2][4][2];
        {
            const int phys = cc ^ gx4;
#pragma unroll
            for (int mt = 0; mt < 4; mt++) {
                int r0 = wm + 16 * mt + g;
                float2 a02 = *(float2*)(smem + SM_A + r0 * 512 + phys * 8);
                float2 a13 = *(float2*)(smem + SM_A + (r0 + 8) * 512 + phys * 8);
                a[0][mt][0] = __float_as_uint(a02.x);
                a[0][mt][1] = __float_as_uint(a13.x);
                a[0][mt][2] = __float_as_uint(a02.y);
                a[0][mt][3] = __float_as_uint(a13.y);
            }
#pragma unroll
            for (int nt = 0; nt < 4; nt++) {
                int n0 = wn + 8 * nt + g;
                float2 b01 = *(float2*)(bufC + n0 * 512 + phys * 8);
                bf[0][nt][0] = __float_as_uint(b01.x);
                bf[0][nt][1] = __float_as_uint(b01.y);
            }
        }

#pragma unroll
        for (int kst = 0; kst < 16; kst++) {
            const int cur = kst & 1, nxt = cur ^ 1;
            if (kst < 15) {
                const int phys = (4 * (kst + 1) + cc) ^ gx4;
#pragma unroll
                for (int mt = 0; mt < 4; mt++) {
                    int r0 = wm + 16 * mt + g;
                    float2 a02 = *(float2*)(smem + SM_A + r0 * 512 + phys * 8);
                    float2 a13 = *(float2*)(smem + SM_A + (r0 + 8) * 512 + phys * 8);
                    a[nxt][mt][0] = __float_as_uint(a02.x);
                    a[nxt][mt][1] = __float_as_uint(a13.x);
                    a[nxt][mt][2] = __float_as_uint(a02.y);
                    a[nxt][mt][3] = __float_as_uint(a13.y);
                }
#pragma unroll
                for (int nt = 0; nt < 4; nt++) {
                    int n0 = wn + 8 * nt + g;
                    float2 b01 = *(float2*)(bufC + n0 * 512 + phys * 8);
                    bf[nxt][nt][0] = __float_as_uint(b01.x);
                    bf[nxt][nt][1] = __float_as_uint(b01.y);
                }
            }
#pragma unroll
            for (int mt = 0; mt < 4; mt++)
#pragma unroll
                for (int nt = 0; nt < 4; nt++) {
                    asm volatile(
                        "mma.sync.aligned.m16n8k8.row.col.f32.tf32.tf32.f32 "
                        "{%0,%1,%2,%3}, {%4,%5,%6,%7}, {%8,%9}, {%0,%1,%2,%3};"
                        : "+f"(acc[mt][nt][0]), "+f"(acc[mt][nt][1]),
                          "+f"(acc[mt][nt][2]), "+f"(acc[mt][nt][3])
                        : "r"(a[cur][mt][0]), "r"(a[cur][mt][1]),
                          "r"(a[cur][mt][2]), "r"(a[cur][mt][3]),
                          "r"(bf[cur][nt][0]), "r"(bf[cur][nt][1]));
                }
        }

        // ---- epilogue: d = sqrt(max(sqi + sqj - 2*dot, 0) + eps) ----
        {
            float2 sqj2[4];
            const int sjb = jj * 128 + wn;
#pragma unroll
            for (int nt = 0; nt < 4; nt++)
                sqj2[nt] = *(const float2*)&sqj_s[sjb + 8 * nt + 2 * cc];
#pragma unroll
            for (int mt = 0; mt < 4; mt++) {
#pragma unroll
                for (int h = 0; h < 2; h++) {
                    int row = wm + 16 * mt + 8 * h + g;
                    float si = sqi_s[row];
                    float* orow = out + ((size_t)(b * N_ + i0 + row)) * N_ +
                                  jbase + jj * 128 + wn;
#pragma unroll
                    for (int nt = 0; nt < 4; nt++) {
                        float d0 = acc[mt][nt][2 * h];
                        float d1 = acc[mt][nt][2 * h + 1];
                        float v0 = fsqrt_approx(fmaxf(fmaf(-2.f, d0, si + sqj2[nt].x), 0.f) + 1e-7f);
                        float v1 = fsqrt_approx(fmaxf(fmaf(-2.f, d1, si + sqj2[nt].y), 0.f) + 1e-7f);
                        *(float2*)(orow + 8 * nt + 2 * cc) = make_float2(v0, v1);
                    }
                }
            }
        }

        if (jj < 7) {
            asm volatile("cp.async.wait_group 0;");
            __syncthreads();
        }
    }
}

extern "C" void kernel_launch(void* const* d_in, const int* in_sizes, int n_in,
                              void* d_out, int out_size) {
    const float* x = (const float*)d_in[0];
    float* out = (float*)d_out;

    prep_kernel<<<B_ * N_ / 8, 256>>>(x);

    cudaFuncSetAttribute(edm_mma_kernel, cudaFuncAttributeMaxDynamicSharedMemorySize, SM_TOTAL);
    dim3 grid(2, 16, B_);
    edm_mma_kernel<<<grid, 256, SM_TOTAL>>>(out);
}